// round 6
// baseline (speedup 1.0000x reference)
#include <cuda_runtime.h>

#define FULL_MASK 0xffffffffu
typedef unsigned long long ull;

// ---- f32x2 packed-math helpers ----
__device__ __forceinline__ ull pk2(float lo, float hi) {
    ull r; asm("mov.b64 %0,{%1,%2};" : "=l"(r) : "f"(lo), "f"(hi)); return r;
}
__device__ __forceinline__ void up2(ull v, float& lo, float& hi) {
    asm("mov.b64 {%0,%1},%2;" : "=f"(lo), "=f"(hi) : "l"(v));
}
__device__ __forceinline__ ull fma2(ull a, ull b, ull c) {
    ull d; asm("fma.rn.f32x2 %0,%1,%2,%3;" : "=l"(d) : "l"(a), "l"(b), "l"(c)); return d;
}
__device__ __forceinline__ ull mul2(ull a, ull b) {
    ull d; asm("mul.rn.f32x2 %0,%1,%2;" : "=l"(d) : "l"(a), "l"(b)); return d;
}
__device__ __forceinline__ float tanh_hw(float x) {
    float y; asm("tanh.approx.f32 %0, %1;" : "=f"(y) : "f"(x)); return y;
}

// Forward-Euler ScaledODENet. TWO batch elements per warp (weights shared,
// states duplicated); 16 CTAs x 32 threads. Each element runs the R3 scheme
// (permuted reduce-scatter, 6 shuffle rounds) with its OWN shuffle stream;
// the two independent chains phase-shift so each element's shuffle latency
// is hidden by the sibling's issue.
__global__ __launch_bounds__(32, 1)
void ode_fe_kernel(const float* __restrict__ x,
                   const float* __restrict__ W1,
                   const float* __restrict__ b1,
                   const float* __restrict__ b2,
                   const float* __restrict__ W2,
                   float* __restrict__ out,
                   int T) {
    constexpr int B = 32;
    const int bA = blockIdx.x * 2;
    const int bB = bA + 1;
    const int l = threadIdx.x;              // owns hidden units l, l+32
    const float inv_sr = 1.0f / 44100.0f;
    const int perm = l & 15;

    // ================= shared weight staging (registers) =================
    const float w0lo = W1[l], w0hi = W1[l + 32];      // W1 row 0 (x weights)
    const float b1lo = b1[l], b1hi = b1[l + 32];

    // W2 rows l, l+32 pre-scaled by 1/sr, slot i holds output (i ^ perm),
    // packed over adjacent slots.
    ull w2pkA[8], w2pkB[8];
#pragma unroll
    for (int m = 0; m < 8; ++m) {
        const int j0 = (2 * m) ^ perm, j1 = (2 * m + 1) ^ perm;
        w2pkA[m] = pk2(W2[l * 16 + j0] * inv_sr,        W2[l * 16 + j1] * inv_sr);
        w2pkB[m] = pk2(W2[(l + 32) * 16 + j0] * inv_sr, W2[(l + 32) * 16 + j1] * inv_sr);
    }

    // W1 state columns (scalar): w1lo[j] feeds U_l, w1hi[j] feeds U_{l+32}
    float w1lo[16], w1hi[16];
#pragma unroll
    for (int j = 0; j < 16; ++j) {
        w1lo[j] = W1[(j + 1) * 64 + l];
        w1hi[j] = W1[(j + 1) * 64 + l + 32];
    }

    // c = W1s^T (b2/sr): per-step constant added to U
    float clo = 0.0f, chi = 0.0f;
#pragma unroll
    for (int j = 0; j < 16; ++j) {
        const float bj = b2[j] * inv_sr;
        clo = fmaf(bj, w1lo[j], clo);
        chi = fmaf(bj, w1hi[j], chi);
    }
    const float b20s = b2[0] * inv_sr;

    // ================= per-element loop-carried state =================
    float UloA = b1lo, UhiA = b1hi, ys0A = 0.0f;
    float UloB = b1lo, UhiB = b1hi, ys0B = 0.0f;

    if (l == 0) { out[bA] = 0.0f; out[bB] = 0.0f; }   // t=0 rows are zeros
    const int nsteps = T - 1;

    // x prefetch per element: 32 timesteps per register, one block ahead
    float xbufA  = (l < nsteps)      ? x[l * B + bA]        : 0.0f;
    float xnextA = (l + 32 < nsteps) ? x[(l + 32) * B + bA] : 0.0f;
    float xbufB  = (l < nsteps)      ? x[l * B + bB]        : 0.0f;
    float xnextB = (l + 32 < nsteps) ? x[(l + 32) * B + bB] : 0.0f;
    float xtA = __shfl_sync(FULL_MASK, xbufA, 0);
    float xtB = __shfl_sync(FULL_MASK, xbufB, 0);

#pragma unroll 1
    for (int t = 0; t < nsteps; ++t) {
        // ---- front: a = U + x*w0 ; h = tanh(a)  (both elements) ----
        const float aloA = fmaf(xtA, w0lo, UloA);
        const float ahiA = fmaf(xtA, w0hi, UhiA);
        const float aloB = fmaf(xtB, w0lo, UloB);
        const float ahiB = fmaf(xtB, w0hi, UhiB);
        const float hloA = tanh_hw(aloA), hhiA = tanh_hw(ahiA);
        const float hloB = tanh_hw(aloB), hhiB = tanh_hw(ahiB);

        // ---- packed per-lane W2 partials in permuted slots ----
        const ull h2loA = pk2(hloA, hloA), h2hiA = pk2(hhiA, hhiA);
        const ull h2loB = pk2(hloB, hloB), h2hiB = pk2(hhiB, hhiB);
        float vA[16], vB[16];
#pragma unroll
        for (int m = 0; m < 8; ++m) {
            const ull pA = fma2(h2loA, w2pkA[m], mul2(h2hiA, w2pkB[m]));
            const ull pB = fma2(h2loB, w2pkA[m], mul2(h2hiB, w2pkB[m]));
            up2(pA, vA[2 * m], vA[2 * m + 1]);
            up2(pB, vB[2 * m], vB[2 * m + 1]);
        }

        // ---- permuted reduce-scatter, two independent shuffle streams ----
        // (phase-shifted: B's round issue hides A's round latency)
#pragma unroll
        for (int i = 0; i < 8; ++i) vA[i] += __shfl_xor_sync(FULL_MASK, vA[i + 8], 8);
#pragma unroll
        for (int i = 0; i < 8; ++i) vB[i] += __shfl_xor_sync(FULL_MASK, vB[i + 8], 8);
#pragma unroll
        for (int i = 0; i < 4; ++i) vA[i] += __shfl_xor_sync(FULL_MASK, vA[i + 4], 4);
#pragma unroll
        for (int i = 0; i < 4; ++i) vB[i] += __shfl_xor_sync(FULL_MASK, vB[i + 4], 4);
#pragma unroll
        for (int i = 0; i < 2; ++i) vA[i] += __shfl_xor_sync(FULL_MASK, vA[i + 2], 2);
#pragma unroll
        for (int i = 0; i < 2; ++i) vB[i] += __shfl_xor_sync(FULL_MASK, vB[i + 2], 2);
        vA[0] += __shfl_xor_sync(FULL_MASK, vA[1], 1);
        vB[0] += __shfl_xor_sync(FULL_MASK, vB[1], 1);
        vA[0] += __shfl_xor_sync(FULL_MASK, vA[0], 16);
        vB[0] += __shfl_xor_sync(FULL_MASK, vB[0], 16);

        // refill / prefetch next xt (independent of everything below)
        if ((t & 31) == 31) {
            xbufA = xnextA; xbufB = xnextB;
            const int tn = t + 33 + l;
            xnextA = (tn < nsteps) ? x[tn * B + bA] : 0.0f;
            xnextB = (tn < nsteps) ? x[tn * B + bB] : 0.0f;
        }
        xtA = __shfl_sync(FULL_MASK, xbufA, (t + 1) & 31);
        xtB = __shfl_sync(FULL_MASK, xbufB, (t + 1) & 31);

        // ---- broadcast: lane j holds d_j; everyone collects all 16 ----
        float dA[16], dB[16];
#pragma unroll
        for (int j = 0; j < 16; ++j) dA[j] = __shfl_sync(FULL_MASK, vA[0], j);
#pragma unroll
        for (int j = 0; j < 16; ++j) dB[j] = __shfl_sync(FULL_MASK, vB[0], j);

        // ---- output channels (off the critical chain) ----
        ys0A += dA[0] + b20s;
        ys0B += dB[0] + b20s;
        if (l == 0) {
            out[(t + 1) * B + bA] = ys0A;
            out[(t + 1) * B + bB] = ys0B;
        }

        // ---- U += sum_j d_j * W1col_j + c  (scalar, 4-wide trees) ----
        {
            float s0 = fmaf(dA[0],  w1lo[0],  clo);
            float s1 = dA[4]  * w1lo[4];
            float s2 = dA[8]  * w1lo[8];
            float s3 = dA[12] * w1lo[12];
            float r0 = fmaf(dA[0],  w1hi[0],  chi);
            float r1 = dA[4]  * w1hi[4];
            float r2 = dA[8]  * w1hi[8];
            float r3 = dA[12] * w1hi[12];
#pragma unroll
            for (int j = 1; j < 4; ++j) {
                s0 = fmaf(dA[j],      w1lo[j],      s0);
                s1 = fmaf(dA[j + 4],  w1lo[j + 4],  s1);
                s2 = fmaf(dA[j + 8],  w1lo[j + 8],  s2);
                s3 = fmaf(dA[j + 12], w1lo[j + 12], s3);
                r0 = fmaf(dA[j],      w1hi[j],      r0);
                r1 = fmaf(dA[j + 4],  w1hi[j + 4],  r1);
                r2 = fmaf(dA[j + 8],  w1hi[j + 8],  r2);
                r3 = fmaf(dA[j + 12], w1hi[j + 12], r3);
            }
            UloA += (s0 + s1) + (s2 + s3);
            UhiA += (r0 + r1) + (r2 + r3);
        }
        {
            float s0 = fmaf(dB[0],  w1lo[0],  clo);
            float s1 = dB[4]  * w1lo[4];
            float s2 = dB[8]  * w1lo[8];
            float s3 = dB[12] * w1lo[12];
            float r0 = fmaf(dB[0],  w1hi[0],  chi);
            float r1 = dB[4]  * w1hi[4];
            float r2 = dB[8]  * w1hi[8];
            float r3 = dB[12] * w1hi[12];
#pragma unroll
            for (int j = 1; j < 4; ++j) {
                s0 = fmaf(dB[j],      w1lo[j],      s0);
                s1 = fmaf(dB[j + 4],  w1lo[j + 4],  s1);
                s2 = fmaf(dB[j + 8],  w1lo[j + 8],  s2);
                s3 = fmaf(dB[j + 12], w1lo[j + 12], s3);
                r0 = fmaf(dB[j],      w1hi[j],      r0);
                r1 = fmaf(dB[j + 4],  w1hi[j + 4],  r1);
                r2 = fmaf(dB[j + 8],  w1hi[j + 8],  r2);
                r3 = fmaf(dB[j + 12], w1hi[j + 12], r3);
            }
            UloB += (s0 + s1) + (s2 + s3);
            UhiB += (r0 + r1) + (r2 + r3);
        }
    }
}

extern "C" void kernel_launch(void* const* d_in, const int* in_sizes, int n_in,
                              void* d_out, int out_size) {
    const float* x  = (const float*)d_in[0];
    const float* W1 = (const float*)d_in[1];
    const float* b1 = (const float*)d_in[2];
    const float* W2 = (const float*)d_in[3];
    const float* b2 = (const float*)d_in[4];
    float* out = (float*)d_out;

    const int T = in_sizes[0] / 32;   // x is (T, B=32, F=1)
    ode_fe_kernel<<<16, 32>>>(x, W1, b1, b2, W2, out, T);
}

// round 8
// speedup vs baseline: 1.4810x; 1.4810x over previous
#include <cuda_runtime.h>

#define FULL_MASK 0xffffffffu
typedef unsigned long long ull;

// ---- f32x2 packed-math helpers ----
__device__ __forceinline__ ull pk2(float lo, float hi) {
    ull r; asm("mov.b64 %0,{%1,%2};" : "=l"(r) : "f"(lo), "f"(hi)); return r;
}
__device__ __forceinline__ void up2(ull v, float& lo, float& hi) {
    asm("mov.b64 {%0,%1},%2;" : "=f"(lo), "=f"(hi) : "l"(v));
}
__device__ __forceinline__ ull fma2(ull a, ull b, ull c) {
    ull d; asm("fma.rn.f32x2 %0,%1,%2,%3;" : "=l"(d) : "l"(a), "l"(b), "l"(c)); return d;
}
__device__ __forceinline__ ull mul2(ull a, ull b) {
    ull d; asm("mul.rn.f32x2 %0,%1,%2;" : "=l"(d) : "l"(a), "l"(b)); return d;
}
__device__ __forceinline__ ull add2(ull a, ull b) {
    ull d; asm("add.rn.f32x2 %0,%1,%2;" : "=l"(d) : "l"(a), "l"(b)); return d;
}
__device__ __forceinline__ float tanh_hw(float x) {
    float y; asm("tanh.approx.f32 %0, %1;" : "=f"(y) : "f"(x)); return y;
}

// Forward-Euler ScaledODENet, one warp per batch element (32 CTAs x 32 thr).
// R5-proven pipeline (fresh a = U + x*w0, U-carry, radix-16 reduce-scatter,
// shfl_xor-16 fold); ONLY the broadcast is new: the folded d (identical in
// lanes l and l^16) is stored once to sm[l&15] and read back as LDS.64
// pairs feeding a horizontal packed W1 tree.
__global__ __launch_bounds__(32, 1)
void ode_fe_kernel(const float* __restrict__ x,
                   const float* __restrict__ W1,
                   const float* __restrict__ b1,
                   const float* __restrict__ b2,
                   const float* __restrict__ W2,
                   float* __restrict__ out,
                   int T) {
    __shared__ float sm[16];

    constexpr int B = 32;
    const int b = blockIdx.x;
    const int l = threadIdx.x;              // owns hidden units l, l+32
    const float inv_sr = 1.0f / 44100.0f;
    const int perm = l & 15;

    // ---- one-time weight staging ----
    const ull w02 = pk2(W1[l], W1[l + 32]);          // W1 row 0 (x weights)

    // W2 rows l, l+32 pre-scaled by 1/sr; slot i holds output (i ^ perm),
    // packed over adjacent slots (2m, 2m+1). [R5-proven layout]
    ull w2A[8], w2B[8];
#pragma unroll
    for (int m = 0; m < 8; ++m) {
        const int j0 = (2 * m) ^ perm, j1 = (2 * m + 1) ^ perm;
        w2A[m] = pk2(W2[l * 16 + j0] * inv_sr,        W2[l * 16 + j1] * inv_sr);
        w2B[m] = pk2(W2[(l + 32) * 16 + j0] * inv_sr, W2[(l + 32) * 16 + j1] * inv_sr);
    }

    // W1 state rows as horizontal pairs per unit (state j -> row j+1):
    // w1plo[m] = (W1[row 2m+1][l], W1[row 2m+2][l]); w1phi for unit l+32.
    ull w1plo[8], w1phi[8];
#pragma unroll
    for (int m = 0; m < 8; ++m) {
        w1plo[m] = pk2(W1[(2 * m + 1) * 64 + l],      W1[(2 * m + 2) * 64 + l]);
        w1phi[m] = pk2(W1[(2 * m + 1) * 64 + l + 32], W1[(2 * m + 2) * 64 + l + 32]);
    }

    // c = W1s^T (b2/sr) per owned unit; tree seeds (c in lo half, 0 in hi)
    float clo = 0.0f, chi = 0.0f;
#pragma unroll
    for (int j = 0; j < 16; ++j) {
        const float bj = b2[j] * inv_sr;
        clo = fmaf(bj, W1[(j + 1) * 64 + l],      clo);
        chi = fmaf(bj, W1[(j + 1) * 64 + l + 32], chi);
    }
    const ull seedlo = pk2(clo, 0.0f);
    const ull seedhi = pk2(chi, 0.0f);
    const float b20s = b2[0] * inv_sr;

    // ---- loop-carried state ----
    ull U2 = pk2(b1[l], b1[l + 32]);        // U = b1 + W1s^T ys (ys starts 0)
    float ys0 = 0.0f;

    if (l == 0) out[b] = 0.0f;              // t=0 output row is zeros
    const int nsteps = T - 1;

    // x prefetch: 32 timesteps per register, one block ahead
    float xbuf  = (l < nsteps)      ? x[l * B + b]        : 0.0f;
    float xnext = (l + 32 < nsteps) ? x[(l + 32) * B + b] : 0.0f;
    float xt = __shfl_sync(FULL_MASK, xbuf, 0);

#pragma unroll 1
    for (int t = 0; t < nsteps; ++t) {
        // ---- a = U + x*w0 ; h = tanh(a)  (fresh x each step) ----
        const ull a2 = fma2(pk2(xt, xt), w02, U2);
        float alo, ahi;
        up2(a2, alo, ahi);
        const float hlo = tanh_hw(alo);
        const float hhi = tanh_hw(ahi);

        // ---- packed per-lane W2 partials in permuted slots ----
        const ull h2lo = pk2(hlo, hlo);
        const ull h2hi = pk2(hhi, hhi);
        float v[16];
#pragma unroll
        for (int m = 0; m < 8; ++m) {
            const ull p2 = fma2(h2lo, w2A[m], mul2(h2hi, w2B[m]));
            up2(p2, v[2 * m], v[2 * m + 1]);
        }

        // ---- radix-16 reduce-scatter: ONE shuffle round + add tree ----
        float g[15];
#pragma unroll
        for (int o = 1; o < 16; ++o)
            g[o - 1] = __shfl_xor_sync(FULL_MASK, v[o], o);
        const float t0 = (g[0] + g[1])   + (g[2] + g[3]);
        const float t1 = (g[4] + g[5])   + (g[6] + g[7]);
        const float t2 = (g[8] + g[9])   + (g[10] + g[11]);
        const float t3 = (g[12] + g[13]) + (g[14] + v[0]);
        float dh = (t0 + t1) + (t2 + t3);   // half-warp sum of output (l&15)

        // ---- fold: lanes l and l^16 now hold bitwise-identical d_{l&15} ----
        dh += __shfl_xor_sync(FULL_MASK, dh, 16);

        // ---- smem broadcast (double-write of identical bits is benign) ----
        sm[perm] = dh;

        // off-chain while the store drains: x refill + next xt
        if ((t & 31) == 31) {
            xbuf = xnext;
            const int tn = t + 33 + l;
            xnext = (tn < nsteps) ? x[tn * B + b] : 0.0f;
        }
        xt = __shfl_sync(FULL_MASK, xbuf, (t + 1) & 31);

        __syncwarp();

        // dp[m] = (d_2m, d_2m+1), complete sums, in every lane
        ull dp[8];
        float d0 = 0.0f;
#pragma unroll
        for (int m = 0; m < 8; ++m) {
            const float2 f = *reinterpret_cast<const float2*>(sm + 2 * m);
            dp[m] = pk2(f.x, f.y);
            if (m == 0) d0 = f.x;
        }

        // ---- output channel (off the critical chain) ----
        ys0 += d0 + b20s;
        if (l == 0) out[(t + 1) * B + b] = ys0;

        // ---- U += sum_m dp[m].w1pairs[m] + c  (horizontal packed dots) ----
        ull sl0 = fma2(dp[0], w1plo[0], seedlo);
        ull sl1 = mul2(dp[4], w1plo[4]);
        ull sh0 = fma2(dp[0], w1phi[0], seedhi);
        ull sh1 = mul2(dp[4], w1phi[4]);
#pragma unroll
        for (int m = 1; m < 4; ++m) {
            sl0 = fma2(dp[m],     w1plo[m],     sl0);
            sl1 = fma2(dp[m + 4], w1plo[m + 4], sl1);
            sh0 = fma2(dp[m],     w1phi[m],     sh0);
            sh1 = fma2(dp[m + 4], w1phi[m + 4], sh1);
        }
        const ull slo2 = add2(sl0, sl1);
        const ull shi2 = add2(sh0, sh1);
        float sx, sy, rx, ry;
        up2(slo2, sx, sy);
        up2(shi2, rx, ry);
        U2 = add2(U2, pk2(sx + sy, rx + ry));

        __syncwarp();   // protect sm[] reuse next iteration
    }
}

extern "C" void kernel_launch(void* const* d_in, const int* in_sizes, int n_in,
                              void* d_out, int out_size) {
    const float* x  = (const float*)d_in[0];
    const float* W1 = (const float*)d_in[1];
    const float* b1 = (const float*)d_in[2];
    const float* W2 = (const float*)d_in[3];
    const float* b2 = (const float*)d_in[4];
    float* out = (float*)d_out;

    const int T = in_sizes[0] / 32;   // x is (T, B=32, F=1)
    ode_fe_kernel<<<32, 32>>>(x, W1, b1, b2, W2, out, T);
}